// round 3
// baseline (speedup 1.0000x reference)
#include <cuda_runtime.h>
#include <cstddef>

// Problem constants
#define BB   16
#define SS   1024
#define DM   256
#define BSN  (BB*SS)             // 16384
#define OUT_ELEMS   (BSN*DM)     // 4,194,304
#define ATTN_ELEMS  (BB*8*SS*SS) // 134,217,728

typedef unsigned long long u64;

__device__ __forceinline__ u64 pk2(float x, float y) {
    u64 r; asm("mov.b64 %0, {%1,%2};" : "=l"(r) : "f"(x), "f"(y)); return r;
}
__device__ __forceinline__ void up2(u64 v, float& x, float& y) {
    asm("mov.b64 {%0,%1}, %2;" : "=f"(x), "=f"(y) : "l"(v));
}
__device__ __forceinline__ void ffma2(u64& d, u64 a, u64 b) {
    asm("fma.rn.f32x2 %0, %1, %2, %0;" : "+l"(d) : "l"(a), "l"(b));
}

// ---------------- scratch (static device memory; no allocation) -------------
__device__ float g_Wq[256*256], g_Wk[256*256], g_Wv[256*256];
__device__ float g_bq[256],     g_bk[256],     g_bv[256];
__device__ float g_Q [BSN*DM];
__device__ float g_K [BSN*DM];
__device__ float g_V [BSN*DM];
__device__ float g_KT[BSN*DM];            // (b, n, s)
__device__ float g_O [BSN*DM];            // concat(o_dist, o_adj)
__device__ float g_Dsm[(size_t)BB*SS*SS]; // softmax(dist + neg)

// ---------------- fused weight packing: 3x ([Wd|Wa] -> 256x256) -------------
__global__ void pack3_kernel(
    const float* __restrict__ Wqd, const float* __restrict__ Wqa,
    const float* __restrict__ bqd, const float* __restrict__ bqa,
    const float* __restrict__ Wkd, const float* __restrict__ Wka,
    const float* __restrict__ bkd, const float* __restrict__ bka,
    const float* __restrict__ Wvd, const float* __restrict__ Wva,
    const float* __restrict__ bvd, const float* __restrict__ bva,
    float* __restrict__ Wq, float* __restrict__ bq,
    float* __restrict__ Wk, float* __restrict__ bk,
    float* __restrict__ Wv, float* __restrict__ bv) {
    int k = blockIdx.x, n = threadIdx.x, w = blockIdx.y;
    const float* Wd = (w == 0) ? Wqd : (w == 1) ? Wkd : Wvd;
    const float* Wa = (w == 0) ? Wqa : (w == 1) ? Wka : Wva;
    const float* bd = (w == 0) ? bqd : (w == 1) ? bkd : bvd;
    const float* ba = (w == 0) ? bqa : (w == 1) ? bka : bva;
    float* W    = (w == 0) ? Wq : (w == 1) ? Wk : Wv;
    float* bias = (w == 0) ? bq : (w == 1) ? bk : bv;
    W[k*256 + n] = (n < 128) ? Wd[k*128 + n] : Wa[k*128 + (n-128)];
    if (k == 0) bias[n] = (n < 128) ? bd[n] : ba[n-128];
}

// ---------------- GEMM: C[16384x256] = A[16384x256] @ W[256x256] + bias -----
// BM=128 BN=64 BK=16, 256 threads, 8x4/thread, double-buffered smem.
__global__ __launch_bounds__(256, 3)
void gemm_kernel(const float* __restrict__ A, const float* __restrict__ W,
                 const float* __restrict__ bias, float* __restrict__ C) {
    __shared__ float As[2][16][132];   // k-major, padded
    __shared__ float Ws[2][16][68];
    const int t  = threadIdx.x;
    const int m0 = blockIdx.x * 128;
    const int n0 = blockIdx.y * 64;
    const int tn = t & 15, tm = t >> 4;

    // loader indices
    const int la_row = t >> 1, la_c4 = (t & 1) * 2;   // A: 2 float4/thread (rows t>>1, k-quads)
    const int lw_k = t >> 4, lw_n4 = t & 15;          // W: 1 float4/thread

    float acc[8][4];
    #pragma unroll
    for (int i = 0; i < 8; ++i)
        #pragma unroll
        for (int j = 0; j < 4; ++j) acc[i][j] = 0.f;

    // prologue: stage 0
    {
        float4 va0 = *(const float4*)(A + (size_t)(m0+la_row)*256 + la_c4*4);
        float4 va1 = *(const float4*)(A + (size_t)(m0+la_row)*256 + la_c4*4 + 4);
        float4 vw  = *(const float4*)(W + (size_t)lw_k*256 + n0 + lw_n4*4);
        As[0][la_c4*4+0][la_row] = va0.x; As[0][la_c4*4+1][la_row] = va0.y;
        As[0][la_c4*4+2][la_row] = va0.z; As[0][la_c4*4+3][la_row] = va0.w;
        As[0][la_c4*4+4][la_row] = va1.x; As[0][la_c4*4+5][la_row] = va1.y;
        As[0][la_c4*4+6][la_row] = va1.z; As[0][la_c4*4+7][la_row] = va1.w;
        *(float4*)(&Ws[0][lw_k][lw_n4*4]) = vw;
    }
    __syncthreads();

    #pragma unroll
    for (int kt = 0; kt < 16; ++kt) {
        const int cur = kt & 1;
        float4 va0, va1, vw;
        if (kt < 15) {
            int k0 = (kt+1)*16;
            va0 = *(const float4*)(A + (size_t)(m0+la_row)*256 + k0 + la_c4*4);
            va1 = *(const float4*)(A + (size_t)(m0+la_row)*256 + k0 + la_c4*4 + 4);
            vw  = *(const float4*)(W + (size_t)(k0+lw_k)*256 + n0 + lw_n4*4);
        }
        #pragma unroll
        for (int k = 0; k < 16; ++k) {
            float a[8];
            float4 b4 = *(const float4*)(&Ws[cur][k][tn*4]);
            #pragma unroll
            for (int i = 0; i < 8; ++i) a[i] = As[cur][k][tm*8 + i];
            #pragma unroll
            for (int i = 0; i < 8; ++i) {
                acc[i][0] = fmaf(a[i], b4.x, acc[i][0]);
                acc[i][1] = fmaf(a[i], b4.y, acc[i][1]);
                acc[i][2] = fmaf(a[i], b4.z, acc[i][2]);
                acc[i][3] = fmaf(a[i], b4.w, acc[i][3]);
            }
        }
        if (kt < 15) {
            const int nxt = cur ^ 1;
            As[nxt][la_c4*4+0][la_row] = va0.x; As[nxt][la_c4*4+1][la_row] = va0.y;
            As[nxt][la_c4*4+2][la_row] = va0.z; As[nxt][la_c4*4+3][la_row] = va0.w;
            As[nxt][la_c4*4+4][la_row] = va1.x; As[nxt][la_c4*4+5][la_row] = va1.y;
            As[nxt][la_c4*4+6][la_row] = va1.z; As[nxt][la_c4*4+7][la_row] = va1.w;
            *(float4*)(&Ws[nxt][lw_k][lw_n4*4]) = vw;
        }
        __syncthreads();
    }

    float4 bb = *(const float4*)(bias + n0 + tn*4);
    #pragma unroll
    for (int i = 0; i < 8; ++i) {
        int m = m0 + tm*8 + i;
        float4 o;
        o.x = acc[i][0] + bb.x; o.y = acc[i][1] + bb.y;
        o.z = acc[i][2] + bb.z; o.w = acc[i][3] + bb.w;
        *(float4*)(C + (size_t)m*256 + n0 + tn*4) = o;
    }
}

// ---------------- prep: dist softmax + K transpose (fused launch) -----------
__global__ __launch_bounds__(256)
void prep_kernel(const float* __restrict__ dist, const float* __restrict__ mask,
                 const float* __restrict__ Kp, float* __restrict__ Dsm,
                 float* __restrict__ KT) {
    __shared__ float tile[32][33];
    __shared__ float ws[8];
    const int blk = blockIdx.x;
    const int t = threadIdx.x;
    if (blk < 16384) {
        // ---- dist softmax row ----
        const int b = blk >> 10, q = blk & 1023;
        const float* drow = dist + ((size_t)b*SS + q)*SS;
        const float* mrow = mask + (size_t)b*SS;
        float e[4], s = 0.f;
        #pragma unroll
        for (int u = 0; u < 4; ++u) {
            int k = t + u*256;
            e[u] = __expf(drow[k] + mrow[k] * -1e9f);
            s += e[u];
        }
        #pragma unroll
        for (int off = 16; off; off >>= 1) s += __shfl_xor_sync(0xffffffffu, s, off);
        if ((t & 31) == 0) ws[t >> 5] = s;
        __syncthreads();
        float tot = 0.f;
        #pragma unroll
        for (int w = 0; w < 8; ++w) tot += ws[w];
        const float inv = 1.f / tot;
        float* orow = Dsm + ((size_t)b*SS + q)*SS;
        #pragma unroll
        for (int u = 0; u < 4; ++u) orow[t + u*256] = e[u] * inv;
    } else {
        // ---- K transpose 32x32 tile ----
        const int r  = (blk - 16384) & 255;
        const int b  = (blk - 16384) >> 8;
        const int n0 = (r & 7) * 32;
        const int s0 = (r >> 3) * 32;
        const int tx = t & 31, ty = t >> 5;   // 32 x 8
        const float* src = Kp + ((size_t)b*SS + s0)*256 + n0;
        #pragma unroll
        for (int i = 0; i < 32; i += 8)
            tile[ty+i][tx] = src[(size_t)(ty+i)*256 + tx];
        __syncthreads();
        float* dst = KT + ((size_t)b*256 + n0)*SS + s0;
        #pragma unroll
        for (int i = 0; i < 32; i += 8)
            dst[(size_t)(ty+i)*SS + tx] = tile[tx][ty+i];
    }
}

// ---------------- fused attention: CTA = 16 queries x 1 head ----------------
// K and V read DIRECTLY from gmem with register double-buffer prefetch.
// Thread owns 8 contiguous keys c = (t&127)*8+j in QK; keys cg+16m in PV.
// smem (floats): q_dup[16][64]=1024 | w_sm[16][1032]=16512 | buf[8208] | pred[64]
__global__ __launch_bounds__(256, 2)
void attn_kernel(const float* __restrict__ Q, const float* __restrict__ KT,
                 const float* __restrict__ V, const float* __restrict__ mask,
                 const float* __restrict__ extraD, const float* __restrict__ extraA,
                 float* __restrict__ attnw, float* __restrict__ Obuf) {
    extern __shared__ float sm[];
    float* q_dup = sm;                 // 1024
    float* w_sm  = sm + 1024;          // 16512
    float* buf   = sm + 17536;         // 8208
    float* pred  = sm + 25744;         // 64

    const int t  = threadIdx.x;
    const int q0 = blockIdx.x * 16;
    const int hg = blockIdx.y;         // 0..7 ; branch = hg>>2
    const int b  = blockIdx.z;
    const int coloff = hg * 32;
    const float* extra = (hg >= 4) ? extraA : extraD;

    if (t < 128) {                     // Q as duplicated pairs (q,q)
        int r = t >> 3, c4 = t & 7;
        float4 v = *(const float4*)(Q + (size_t)(b*SS + q0 + r)*256 + coloff + c4*4);
        float* d = q_dup + r*64 + c4*8;
        float4 o;
        o.x = v.x; o.y = v.x; o.z = v.y; o.w = v.y; *(float4*)(d)     = o;
        o.x = v.z; o.y = v.z; o.z = v.w; o.w = v.w; *(float4*)(d + 4) = o;
    }
    __syncthreads();

    const int rt = t >> 7;            // row group: rows rt*8..rt*8+7
    const int kt = t & 127;           // keys kt*8 .. kt*8+7

    u64 acc[8][4];
    #pragma unroll
    for (int i = 0; i < 8; ++i)
        #pragma unroll
        for (int jp = 0; jp < 4; ++jp) acc[i][jp] = 0ull;

    // ---- QK^T : K direct from gmem, prefetch 2 dims ahead ----
    const float* kt_ptr = KT + ((size_t)b*256 + coloff)*SS + kt*8;
    ulonglong2 kb[2][2][2];   // [buf][dd-in-chunk][half]
    #pragma unroll
    for (int dd = 0; dd < 2; ++dd) {
        kb[0][dd][0] = *(const ulonglong2*)(kt_ptr + (size_t)dd*SS);
        kb[0][dd][1] = *(const ulonglong2*)(kt_ptr + (size_t)dd*SS + 4);
    }
    #pragma unroll
    for (int dc = 0; dc < 16; ++dc) {           // 16 chunks x 2 dims
        const int cb = dc & 1, nb = cb ^ 1;
        if (dc < 15) {
            #pragma unroll
            for (int dd = 0; dd < 2; ++dd) {
                kb[nb][dd][0] = *(const ulonglong2*)(kt_ptr + (size_t)(dc*2+2+dd)*SS);
                kb[nb][dd][1] = *(const ulonglong2*)(kt_ptr + (size_t)(dc*2+2+dd)*SS + 4);
            }
        }
        #pragma unroll
        for (int dd = 0; dd < 2; ++dd) {
            u64 kp[4] = {kb[cb][dd][0].x, kb[cb][dd][0].y,
                         kb[cb][dd][1].x, kb[cb][dd][1].y};
            #pragma unroll
            for (int i = 0; i < 8; ++i) {
                u64 qd = *(const u64*)(&q_dup[(rt*8+i)*64 + (dc*2+dd)*2]);
                #pragma unroll
                for (int jp = 0; jp < 4; ++jp) ffma2(acc[i][jp], qd, kp[jp]);
            }
        }
    }

    // ---- softmax (masked lanes underflow to exact 0) ----
    const float scale = 0.17677669529663688f;  // 1/sqrt(32)
    float neg[8];
    {
        float4 m0v = *(const float4*)(mask + b*SS + kt*8);
        float4 m1v = *(const float4*)(mask + b*SS + kt*8 + 4);
        neg[0]=m0v.x*-1e9f; neg[1]=m0v.y*-1e9f; neg[2]=m0v.z*-1e9f; neg[3]=m0v.w*-1e9f;
        neg[4]=m1v.x*-1e9f; neg[5]=m1v.y*-1e9f; neg[6]=m1v.z*-1e9f; neg[7]=m1v.w*-1e9f;
    }
    float psum[8];
    #pragma unroll
    for (int i = 0; i < 8; ++i) {
        float e[8];
        #pragma unroll
        for (int jp = 0; jp < 4; ++jp) up2(acc[i][jp], e[2*jp], e[2*jp+1]);
        float s = 0.f;
        #pragma unroll
        for (int j = 0; j < 8; ++j) {
            e[j] = __expf(fmaf(e[j], scale, neg[j]));
            s += e[j];
        }
        #pragma unroll
        for (int jp = 0; jp < 4; ++jp) acc[i][jp] = pk2(e[2*jp], e[2*jp+1]);
        #pragma unroll
        for (int off = 16; off; off >>= 1) s += __shfl_xor_sync(0xffffffffu, s, off);
        psum[i] = s;
    }
    const int widx = (t >> 5) & 3;
    if ((t & 31) == 0) {
        #pragma unroll
        for (int i = 0; i < 8; ++i) pred[(rt*4 + widx)*8 + i] = psum[i];
    }
    __syncthreads();
    float inv[8];
    #pragma unroll
    for (int i = 0; i < 8; ++i)
        inv[i] = 1.f / (pred[(rt*4+0)*8+i] + pred[(rt*4+1)*8+i] +
                        pred[(rt*4+2)*8+i] + pred[(rt*4+3)*8+i]);

    // ---- weighting: w = p * inv * extra -> w_sm + attn_w (vectorized) ----
    #pragma unroll
    for (int i = 0; i < 8; ++i) {
        int r = rt*8 + i;
        int qrow = q0 + r;
        const float* ex = extra + ((size_t)b*SS + qrow)*SS + kt*8;
        float4 e0 = *(const float4*)(ex);
        float4 e1 = *(const float4*)(ex + 4);
        float ev[8] = {e0.x, e0.y, e0.z, e0.w, e1.x, e1.y, e1.z, e1.w};
        float w[8];
        #pragma unroll
        for (int jp = 0; jp < 4; ++jp) up2(acc[i][jp], w[2*jp], w[2*jp+1]);
        float4 o0, o1;
        o0.x = w[0]*inv[i]*ev[0]; o0.y = w[1]*inv[i]*ev[1];
        o0.z = w[2]*inv[i]*ev[2]; o0.w = w[3]*inv[i]*ev[3];
        o1.x = w[4]*inv[i]*ev[4]; o1.y = w[5]*inv[i]*ev[5];
        o1.z = w[6]*inv[i]*ev[6]; o1.w = w[7]*inv[i]*ev[7];
        *(float4*)(&w_sm[r*1032 + kt*8])     = o0;
        *(float4*)(&w_sm[r*1032 + kt*8 + 4]) = o1;
        if (attnw) {
            float* wout = attnw + (((size_t)(b*8 + hg)*SS + qrow)*SS) + kt*8;
            *(float4*)(wout)     = o0;
            *(float4*)(wout + 4) = o1;
        }
    }
    __syncthreads();

    // ---- PV: out[16][32] = w_sm @ V, V direct from gmem w/ prefetch ----
    const int cg = t & 15, dg = (t >> 4) & 7, rg = t >> 7;
    u64 oac[8][2];
    #pragma unroll
    for (int i = 0; i < 8; ++i) { oac[i][0] = 0ull; oac[i][1] = 0ull; }

    const float* vrow = V + ((size_t)(b*SS + cg))*256 + coloff + dg*4;
    ulonglong2 vp[2];
    vp[0] = *(const ulonglong2*)(vrow);
    #pragma unroll 8
    for (int m = 0; m < 64; ++m) {
        if (m < 63) vp[(m+1)&1] = *(const ulonglong2*)(vrow + (size_t)(m+1)*16*256);
        const u64 v0 = vp[m&1].x, v1 = vp[m&1].y;
        const int kc = cg + 16*m;
        #pragma unroll
        for (int i = 0; i < 8; ++i) {
            float w = w_sm[(rg*8+i)*1032 + kc];
            u64 wd = pk2(w, w);
            ffma2(oac[i][0], wd, v0);
            ffma2(oac[i][1], wd, v1);
        }
    }
    #pragma unroll
    for (int i = 0; i < 8; ++i) {
        float o0, o1, o2, o3;
        up2(oac[i][0], o0, o1);
        up2(oac[i][1], o2, o3);
        float* d = &buf[cg*513 + (rg*8+i)*32 + dg*4];
        d[0] = o0; d[1] = o1; d[2] = o2; d[3] = o3;
    }
    __syncthreads();
    #pragma unroll
    for (int u = 0; u < 2; ++u) {
        int slot = t + u*256;
        float s = 0.f;
        #pragma unroll
        for (int g = 0; g < 16; ++g) s += buf[g*513 + slot];
        int r = slot >> 5, d = slot & 31;
        Obuf[(size_t)(b*SS + q0 + r)*256 + coloff + d] = s;
    }
}

// ---------------- launch --------------------------------------------------
extern "C" void kernel_launch(void* const* d_in, const int* in_sizes, int n_in,
                              void* d_out, int out_size) {
    const float* v_ori = (const float*)d_in[0];
    const float* k_ori = (const float*)d_in[1];
    const float* q_ori = (const float*)d_in[2];
    const float* mask  = (const float*)d_in[3];
    const float* adj   = (const float*)d_in[4];
    const float* dist  = (const float*)d_in[5];
    const float* Wq_d = (const float*)d_in[6];  const float* bq_d = (const float*)d_in[7];
    const float* Wk_d = (const float*)d_in[8];  const float* bk_d = (const float*)d_in[9];
    const float* Wv_d = (const float*)d_in[10]; const float* bv_d = (const float*)d_in[11];
    const float* Wq_a = (const float*)d_in[12]; const float* bq_a = (const float*)d_in[13];
    const float* Wk_a = (const float*)d_in[14]; const float* bk_a = (const float*)d_in[15];
    const float* Wv_a = (const float*)d_in[16]; const float* bv_a = (const float*)d_in[17];
    const float* Wo   = (const float*)d_in[18]; const float* bo   = (const float*)d_in[19];

    float* out   = (float*)d_out;
    float* attnw = (out_size >= OUT_ELEMS + ATTN_ELEMS) ? out + OUT_ELEMS : nullptr;

    float *pWq,*pWk,*pWv,*pbq,*pbk,*pbv,*pQ,*pK,*pV,*pKT,*pO,*pD;
    cudaGetSymbolAddress((void**)&pWq, g_Wq);
    cudaGetSymbolAddress((void**)&pWk, g_Wk);
    cudaGetSymbolAddress((void**)&pWv, g_Wv);
    cudaGetSymbolAddress((void**)&pbq, g_bq);
    cudaGetSymbolAddress((void**)&pbk, g_bk);
    cudaGetSymbolAddress((void**)&pbv, g_bv);
    cudaGetSymbolAddress((void**)&pQ,  g_Q);
    cudaGetSymbolAddress((void**)&pK,  g_K);
    cudaGetSymbolAddress((void**)&pV,  g_V);
    cudaGetSymbolAddress((void**)&pKT, g_KT);
    cudaGetSymbolAddress((void**)&pO,  g_O);
    cudaGetSymbolAddress((void**)&pD,  g_Dsm);

    // launch #0: fused pack
    pack3_kernel<<<dim3(256, 3), 256>>>(Wq_d, Wq_a, bq_d, bq_a,
                                        Wk_d, Wk_a, bk_d, bk_a,
                                        Wv_d, Wv_a, bv_d, bv_a,
                                        pWq, pbq, pWk, pbk, pWv, pbv);
    // launches #1-3: projections
    dim3 ggrid(128, 4);
    gemm_kernel<<<ggrid, 256>>>(q_ori, pWq, pbq, pQ);
    gemm_kernel<<<ggrid, 256>>>(k_ori, pWk, pbk, pK);
    gemm_kernel<<<ggrid, 256>>>(v_ori, pWv, pbv, pV);

    // launch #4: fused dist-softmax (16384 blocks) + K-transpose (4096 blocks)
    prep_kernel<<<16384 + 4096, 256>>>(dist, mask, pK, pD, pKT);

    // launch #5: fused attention (profiled by ncu -s 5 -c 1)
    const int SMEM_BYTES = 25808 * 4;   // 103,232 B -> 2 CTAs/SM
    cudaFuncSetAttribute(attn_kernel, cudaFuncAttributeMaxDynamicSharedMemorySize, SMEM_BYTES);
    dim3 agrid(64, 8, 16);
    attn_kernel<<<agrid, 256, SMEM_BYTES>>>(pQ, pKT, pV, mask, pD, adj, attnw, pO);

    // launch #6: output projection
    gemm_kernel<<<ggrid, 256>>>(pO, Wo, bo, out);
}

// round 4
// speedup vs baseline: 1.4521x; 1.4521x over previous
#include <cuda_runtime.h>
#include <cstddef>

// Problem constants
#define BB   16
#define SS   1024
#define DM   256
#define BSN  (BB*SS)             // 16384
#define OUT_ELEMS   (BSN*DM)     // 4,194,304
#define ATTN_ELEMS  (BB*8*SS*SS) // 134,217,728

typedef unsigned long long u64;

__device__ __forceinline__ u64 pk2(float x, float y) {
    u64 r; asm("mov.b64 %0, {%1,%2};" : "=l"(r) : "f"(x), "f"(y)); return r;
}
__device__ __forceinline__ void up2(u64 v, float& x, float& y) {
    asm("mov.b64 {%0,%1}, %2;" : "=f"(x), "=f"(y) : "l"(v));
}
__device__ __forceinline__ void ffma2(u64& d, u64 a, u64 b) {
    asm("fma.rn.f32x2 %0, %1, %2, %0;" : "+l"(d) : "l"(a), "l"(b));
}
__device__ __forceinline__ float to_tf32(float x) {
    float r; asm("cvt.rna.tf32.f32 %0, %1;" : "=f"(r) : "f"(x)); return r;
}
__device__ __forceinline__ void mma_tf32(float* d, float a0, float a1, float a2, float a3,
                                         float b0, float b1) {
    asm("mma.sync.aligned.m16n8k8.row.col.f32.tf32.tf32.f32 "
        "{%0,%1,%2,%3}, {%4,%5,%6,%7}, {%8,%9}, {%0,%1,%2,%3};"
        : "+f"(d[0]), "+f"(d[1]), "+f"(d[2]), "+f"(d[3])
        : "r"(__float_as_uint(a0)), "r"(__float_as_uint(a1)),
          "r"(__float_as_uint(a2)), "r"(__float_as_uint(a3)),
          "r"(__float_as_uint(b0)), "r"(__float_as_uint(b1)));
}

// ---------------- scratch (static device memory; no allocation) -------------
__device__ float g_Wq[256*256], g_Wk[256*256], g_Wv[256*256];
__device__ float g_bq[256],     g_bk[256],     g_bv[256];
__device__ float g_Q [BSN*DM];
__device__ float g_K [BSN*DM];
__device__ float g_V [BSN*DM];
__device__ float g_KT[BSN*DM];            // (b, n, s)
__device__ float g_O [BSN*DM];            // concat(o_dist, o_adj)
__device__ float g_Dsm[(size_t)BB*SS*SS]; // softmax(dist + neg)

// ---------------- fused weight packing ---------------------------------------
__global__ void pack3_kernel(
    const float* __restrict__ Wqd, const float* __restrict__ Wqa,
    const float* __restrict__ bqd, const float* __restrict__ bqa,
    const float* __restrict__ Wkd, const float* __restrict__ Wka,
    const float* __restrict__ bkd, const float* __restrict__ bka,
    const float* __restrict__ Wvd, const float* __restrict__ Wva,
    const float* __restrict__ bvd, const float* __restrict__ bva,
    float* __restrict__ Wq, float* __restrict__ bq,
    float* __restrict__ Wk, float* __restrict__ bk,
    float* __restrict__ Wv, float* __restrict__ bv) {
    int k = blockIdx.x, n = threadIdx.x, w = blockIdx.y;
    const float* Wd = (w == 0) ? Wqd : (w == 1) ? Wkd : Wvd;
    const float* Wa = (w == 0) ? Wqa : (w == 1) ? Wka : Wva;
    const float* bd = (w == 0) ? bqd : (w == 1) ? bkd : bvd;
    const float* ba = (w == 0) ? bqa : (w == 1) ? bka : bva;
    float* W    = (w == 0) ? Wq : (w == 1) ? Wk : Wv;
    float* bias = (w == 0) ? bq : (w == 1) ? bk : bv;
    W[k*256 + n] = (n < 128) ? Wd[k*128 + n] : Wa[k*128 + (n-128)];
    if (k == 0) bias[n] = (n < 128) ? bd[n] : ba[n-128];
}

// ---------------- GEMM (R2 gemm2, measured 58us): 128x128, FFMA2 ------------
__global__ __launch_bounds__(256)
void gemm2_kernel(const float* __restrict__ A, const float* __restrict__ W,
                  const float* __restrict__ bias, float* __restrict__ C) {
    __shared__ float As[16][132];
    __shared__ float Ws[16][132];
    const int t  = threadIdx.x;
    const int m0 = blockIdx.x * 128;
    const int n0 = blockIdx.y * 128;
    const int tn = t & 15, tm = t >> 4;

    u64 acc[4][8];
    #pragma unroll
    for (int p = 0; p < 4; ++p)
        #pragma unroll
        for (int j = 0; j < 8; ++j) acc[p][j] = 0ull;

    for (int k0 = 0; k0 < 256; k0 += 16) {
        __syncthreads();
        #pragma unroll
        for (int u = 0; u < 2; ++u) {
            int fi  = t + u*256;
            int row = fi >> 2, c4 = fi & 3;
            float4 v = *(const float4*)(A + (size_t)(m0+row)*256 + k0 + c4*4);
            As[c4*4+0][row] = v.x; As[c4*4+1][row] = v.y;
            As[c4*4+2][row] = v.z; As[c4*4+3][row] = v.w;
        }
        #pragma unroll
        for (int u = 0; u < 2; ++u) {
            int fi = t + u*256;
            int k = fi >> 5, n4 = fi & 31;
            *(float4*)(&Ws[k][n4*4]) =
                *(const float4*)(W + (size_t)(k0+k)*256 + n0 + n4*4);
        }
        __syncthreads();
        #pragma unroll
        for (int k = 0; k < 16; ++k) {
            ulonglong2 a01 = *(const ulonglong2*)(&As[k][tm*8]);
            ulonglong2 a23 = *(const ulonglong2*)(&As[k][tm*8 + 4]);
            u64 ap[4] = {a01.x, a01.y, a23.x, a23.y};
            float4 w0 = *(const float4*)(&Ws[k][tn*8]);
            float4 w1 = *(const float4*)(&Ws[k][tn*8 + 4]);
            u64 bd[8];
            bd[0] = pk2(w0.x, w0.x); bd[1] = pk2(w0.y, w0.y);
            bd[2] = pk2(w0.z, w0.z); bd[3] = pk2(w0.w, w0.w);
            bd[4] = pk2(w1.x, w1.x); bd[5] = pk2(w1.y, w1.y);
            bd[6] = pk2(w1.z, w1.z); bd[7] = pk2(w1.w, w1.w);
            #pragma unroll
            for (int p = 0; p < 4; ++p)
                #pragma unroll
                for (int j = 0; j < 8; ++j)
                    ffma2(acc[p][j], ap[p], bd[j]);
        }
    }
    float4 b0 = *(const float4*)(bias + n0 + tn*8);
    float4 b1 = *(const float4*)(bias + n0 + tn*8 + 4);
    float bb[8] = {b0.x, b0.y, b0.z, b0.w, b1.x, b1.y, b1.z, b1.w};
    #pragma unroll
    for (int p = 0; p < 4; ++p) {
        float lo[8], hi[8];
        #pragma unroll
        for (int j = 0; j < 8; ++j) up2(acc[p][j], lo[j], hi[j]);
        int r0 = m0 + tm*8 + p*2;
        float4 o;
        o.x = lo[0]+bb[0]; o.y = lo[1]+bb[1]; o.z = lo[2]+bb[2]; o.w = lo[3]+bb[3];
        *(float4*)(C + (size_t)r0*256 + n0 + tn*8) = o;
        o.x = lo[4]+bb[4]; o.y = lo[5]+bb[5]; o.z = lo[6]+bb[6]; o.w = lo[7]+bb[7];
        *(float4*)(C + (size_t)r0*256 + n0 + tn*8 + 4) = o;
        o.x = hi[0]+bb[0]; o.y = hi[1]+bb[1]; o.z = hi[2]+bb[2]; o.w = hi[3]+bb[3];
        *(float4*)(C + (size_t)(r0+1)*256 + n0 + tn*8) = o;
        o.x = hi[4]+bb[4]; o.y = hi[5]+bb[5]; o.z = hi[6]+bb[6]; o.w = hi[7]+bb[7];
        *(float4*)(C + (size_t)(r0+1)*256 + n0 + tn*8 + 4) = o;
    }
}

// ---------------- prep: dist softmax + K transpose (fused launch) -----------
__global__ __launch_bounds__(256)
void prep_kernel(const float* __restrict__ dist, const float* __restrict__ mask,
                 const float* __restrict__ Kp, float* __restrict__ Dsm,
                 float* __restrict__ KT) {
    __shared__ float tile[32][33];
    __shared__ float ws[8];
    const int blk = blockIdx.x;
    const int t = threadIdx.x;
    if (blk < 16384) {
        const int b = blk >> 10, q = blk & 1023;
        const float* drow = dist + ((size_t)b*SS + q)*SS;
        const float* mrow = mask + (size_t)b*SS;
        float e[4], s = 0.f;
        #pragma unroll
        for (int u = 0; u < 4; ++u) {
            int k = t + u*256;
            e[u] = __expf(drow[k] + mrow[k] * -1e9f);
            s += e[u];
        }
        #pragma unroll
        for (int off = 16; off; off >>= 1) s += __shfl_xor_sync(0xffffffffu, s, off);
        if ((t & 31) == 0) ws[t >> 5] = s;
        __syncthreads();
        float tot = 0.f;
        #pragma unroll
        for (int w = 0; w < 8; ++w) tot += ws[w];
        const float inv = 1.f / tot;
        float* orow = Dsm + ((size_t)b*SS + q)*SS;
        #pragma unroll
        for (int u = 0; u < 4; ++u) orow[t + u*256] = e[u] * inv;
    } else {
        const int r  = (blk - 16384) & 255;
        const int b  = (blk - 16384) >> 8;
        const int n0 = (r & 7) * 32;
        const int s0 = (r >> 3) * 32;
        const int tx = t & 31, ty = t >> 5;
        const float* src = Kp + ((size_t)b*SS + s0)*256 + n0;
        #pragma unroll
        for (int i = 0; i < 32; i += 8)
            tile[ty+i][tx] = src[(size_t)(ty+i)*256 + tx];
        __syncthreads();
        float* dst = KT + ((size_t)b*256 + n0)*SS + s0;
        #pragma unroll
        for (int i = 0; i < 32; i += 8)
            dst[(size_t)(ty+i)*SS + tx] = tile[tx][ty+i];
    }
}

// ---------------- fused attention via mma.sync tf32 -------------------------
// CTA = 16 queries x 1 head x full 1024 keys. 8 warps.
// QK: M=16 N=1024(128/warp) K=32 via m16n8k8; softmax; w->attn_w+smem; PV k-split.
// smem floats: q_sm[16*36]=576 | w_sm[16*1036]=16576 | bufA 8256 | msk 1024 | pred 128
__global__ __launch_bounds__(256, 2)
void attn_kernel(const float* __restrict__ Q, const float* __restrict__ KT,
                 const float* __restrict__ V, const float* __restrict__ mask,
                 const float* __restrict__ extraD, const float* __restrict__ extraA,
                 float* __restrict__ attnw, float* __restrict__ Obuf) {
    extern __shared__ float sm[];
    float* q_sm = sm;              // 576
    float* w_sm = sm + 576;        // 16576 (row stride 1036)
    float* bufA = sm + 17152;      // 8256 (K-stage stride 1032 / V-stage stride 36 / partials stride 544)
    float* msk  = sm + 25408;     // 1024
    float* pred = sm + 26432;     // 128

    const int t    = threadIdx.x;
    const int lane = t & 31, warp = t >> 5;
    const int g = lane >> 2, c = lane & 3;     // mma row-group / thread-in-group
    const int q0 = blockIdx.x * 16;
    const int hg = blockIdx.y;
    const int b  = blockIdx.z;
    const int coloff = hg * 32;
    const float* extra = (hg >= 4) ? extraA : extraD;

    // load Q tile (tf32-rounded) and mask*-1e9
    #pragma unroll
    for (int u = 0; u < 2; ++u) {
        int i = t + u*256;
        int r = i >> 5, d = i & 31;
        q_sm[r*36 + d] = to_tf32(Q[(size_t)(b*SS + q0 + r)*256 + coloff + d]);
    }
    #pragma unroll
    for (int u = 0; u < 4; ++u)
        msk[t + u*256] = mask[b*SS + t + u*256] * -1e9f;

    // ---- QK^T ----
    float acc[16][4];
    #pragma unroll
    for (int nt = 0; nt < 16; ++nt)
        #pragma unroll
        for (int j = 0; j < 4; ++j) acc[nt][j] = 0.f;

    const float* ktb = KT + ((size_t)b*256 + coloff)*SS;
    #pragma unroll
    for (int dc = 0; dc < 4; ++dc) {
        __syncthreads();
        const float* src = ktb + (size_t)dc*8*SS;
        #pragma unroll
        for (int u = 0; u < 8; ++u) {       // stage 8 dims x 1024 keys (tf32)
            int fi = t + u*256;
            int kr = fi >> 8, c4 = fi & 255;
            float4 v = *(const float4*)(src + (size_t)kr*SS + c4*4);
            v.x = to_tf32(v.x); v.y = to_tf32(v.y);
            v.z = to_tf32(v.z); v.w = to_tf32(v.w);
            *(float4*)(&bufA[kr*1032 + c4*4]) = v;
        }
        __syncthreads();
        float a0 = q_sm[g*36 + dc*8 + c];
        float a1 = q_sm[(g+8)*36 + dc*8 + c];
        float a2 = q_sm[g*36 + dc*8 + c + 4];
        float a3 = q_sm[(g+8)*36 + dc*8 + c + 4];
        #pragma unroll
        for (int nt = 0; nt < 16; ++nt) {
            int n0 = warp*128 + nt*8 + g;
            float b0 = bufA[c*1032 + n0];
            float b1 = bufA[(c+4)*1032 + n0];
            mma_tf32(acc[nt], a0, a1, a2, a3, b0, b1);
        }
    }

    // ---- softmax (masked lanes: exp underflows to exact 0) ----
    const float scale = 0.17677669529663688f;  // 1/sqrt(32)
    float s_lo = 0.f, s_hi = 0.f;
    #pragma unroll
    for (int nt = 0; nt < 16; ++nt) {
        int key0 = warp*128 + nt*8 + c*2;
        float n0v = msk[key0], n1v = msk[key0+1];
        float e0 = __expf(fmaf(acc[nt][0], scale, n0v));
        float e1 = __expf(fmaf(acc[nt][1], scale, n1v));
        float e2 = __expf(fmaf(acc[nt][2], scale, n0v));
        float e3 = __expf(fmaf(acc[nt][3], scale, n1v));
        acc[nt][0] = e0; acc[nt][1] = e1; acc[nt][2] = e2; acc[nt][3] = e3;
        s_lo += e0 + e1; s_hi += e2 + e3;
    }
    s_lo += __shfl_xor_sync(0xffffffffu, s_lo, 1);
    s_lo += __shfl_xor_sync(0xffffffffu, s_lo, 2);
    s_hi += __shfl_xor_sync(0xffffffffu, s_hi, 1);
    s_hi += __shfl_xor_sync(0xffffffffu, s_hi, 2);
    if (c == 0) {
        pred[warp*16 + g]     = s_lo;
        pred[warp*16 + 8 + g] = s_hi;
    }
    __syncthreads();
    float tlo = 0.f, thi = 0.f;
    #pragma unroll
    for (int w = 0; w < 8; ++w) { tlo += pred[w*16 + g]; thi += pred[w*16 + 8 + g]; }
    const float inv_lo = 1.f / tlo, inv_hi = 1.f / thi;

    // ---- weighting: w = p*inv*extra -> attn_w (exact) + w_sm (tf32) ----
    const float* exlo = extra + ((size_t)b*SS + q0 + g)*SS;
    const float* exhi = extra + ((size_t)b*SS + q0 + 8 + g)*SS;
    float* wlo = attnw ? attnw + ((size_t)(b*8 + hg)*SS + q0 + g)*SS : (float*)0;
    float* whi = attnw ? attnw + ((size_t)(b*8 + hg)*SS + q0 + 8 + g)*SS : (float*)0;
    #pragma unroll
    for (int nt = 0; nt < 16; ++nt) {
        int key0 = warp*128 + nt*8 + c*2;
        float2 elo = *(const float2*)(exlo + key0);
        float2 ehi = *(const float2*)(exhi + key0);
        float w0 = acc[nt][0]*inv_lo*elo.x, w1 = acc[nt][1]*inv_lo*elo.y;
        float w2 = acc[nt][2]*inv_hi*ehi.x, w3 = acc[nt][3]*inv_hi*ehi.y;
        if (wlo) {
            float2 o; o.x = w0; o.y = w1; *(float2*)(wlo + key0) = o;
            o.x = w2; o.y = w3; *(float2*)(whi + key0) = o;
        }
        float2 s; s.x = to_tf32(w0); s.y = to_tf32(w1);
        *(float2*)(&w_sm[g*1036 + key0]) = s;
        s.x = to_tf32(w2); s.y = to_tf32(w3);
        *(float2*)(&w_sm[(g+8)*1036 + key0]) = s;
    }
    __syncthreads();   // w_sm ready; bufA free for V staging

    // ---- PV: out[16][32] = w @ V, m16n8k8, warps k-split ----
    float oc[4][4];
    #pragma unroll
    for (int nt = 0; nt < 4; ++nt)
        #pragma unroll
        for (int j = 0; j < 4; ++j) oc[nt][j] = 0.f;

    const float* vbase = V + (size_t)b*SS*256 + coloff;
    for (int st = 0; st < 8; ++st) {
        __syncthreads();
        #pragma unroll
        for (int u = 0; u < 4; ++u) {       // stage 128 keys x 32 dims (tf32)
            int fi = t + u*256;
            int kr = fi >> 3, q4 = fi & 7;
            float4 v = *(const float4*)(vbase + (size_t)(st*128 + kr)*256 + q4*4);
            v.x = to_tf32(v.x); v.y = to_tf32(v.y);
            v.z = to_tf32(v.z); v.w = to_tf32(v.w);
            *(float4*)(&bufA[kr*36 + q4*4]) = v;
        }
        __syncthreads();
        #pragma unroll
        for (int j = 0; j < 2; ++j) {
            int kb   = (warp*2 + j)*8;       // local key base within stage
            int gkey = st*128 + kb;          // global key base
            float a0 = w_sm[g*1036 + gkey + c];
            float a1 = w_sm[(g+8)*1036 + gkey + c];
            float a2 = w_sm[g*1036 + gkey + c + 4];
            float a3 = w_sm[(g+8)*1036 + gkey + c + 4];
            #pragma unroll
            for (int nt = 0; nt < 4; ++nt) {
                float b0 = bufA[(kb + c)*36 + nt*8 + g];
                float b1 = bufA[(kb + c + 4)*36 + nt*8 + g];
                mma_tf32(oc[nt], a0, a1, a2, a3, b0, b1);
            }
        }
    }

    // ---- cross-warp k-reduction via smem ----
    __syncthreads();                         // bufA free; partials: [8][16*34]
    #pragma unroll
    for (int nt = 0; nt < 4; ++nt) {
        float2 o;
        o.x = oc[nt][0]; o.y = oc[nt][1];
        *(float2*)(&bufA[warp*544 + g*34 + nt*8 + c*2]) = o;
        o.x = oc[nt][2]; o.y = oc[nt][3];
        *(float2*)(&bufA[warp*544 + (g+8)*34 + nt*8 + c*2]) = o;
    }
    __syncthreads();
    #pragma unroll
    for (int u = 0; u < 2; ++u) {
        int slot = t + u*256;
        int r = slot >> 5, d = slot & 31;
        float s = 0.f;
        #pragma unroll
        for (int w = 0; w < 8; ++w) s += bufA[w*544 + r*34 + d];
        Obuf[(size_t)(b*SS + q0 + r)*256 + coloff + d] = s;
    }
}

// ---------------- launch --------------------------------------------------
extern "C" void kernel_launch(void* const* d_in, const int* in_sizes, int n_in,
                              void* d_out, int out_size) {
    const float* v_ori = (const float*)d_in[0];
    const float* k_ori = (const float*)d_in[1];
    const float* q_ori = (const float*)d_in[2];
    const float* mask  = (const float*)d_in[3];
    const float* adj   = (const float*)d_in[4];
    const float* dist  = (const float*)d_in[5];
    const float* Wq_d = (const float*)d_in[6];  const float* bq_d = (const float*)d_in[7];
    const float* Wk_d = (const float*)d_in[8];  const float* bk_d = (const float*)d_in[9];
    const float* Wv_d = (const float*)d_in[10]; const float* bv_d = (const float*)d_in[11];
    const float* Wq_a = (const float*)d_in[12]; const float* bq_a = (const float*)d_in[13];
    const float* Wk_a = (const float*)d_in[14]; const float* bk_a = (const float*)d_in[15];
    const float* Wv_a = (const float*)d_in[16]; const float* bv_a = (const float*)d_in[17];
    const float* Wo   = (const float*)d_in[18]; const float* bo   = (const float*)d_in[19];

    float* out   = (float*)d_out;
    float* attnw = (out_size >= OUT_ELEMS + ATTN_ELEMS) ? out + OUT_ELEMS : (float*)0;

    float *pWq,*pWk,*pWv,*pbq,*pbk,*pbv,*pQ,*pK,*pV,*pKT,*pO,*pD;
    cudaGetSymbolAddress((void**)&pWq, g_Wq);
    cudaGetSymbolAddress((void**)&pWk, g_Wk);
    cudaGetSymbolAddress((void**)&pWv, g_Wv);
    cudaGetSymbolAddress((void**)&pbq, g_bq);
    cudaGetSymbolAddress((void**)&pbk, g_bk);
    cudaGetSymbolAddress((void**)&pbv, g_bv);
    cudaGetSymbolAddress((void**)&pQ,  g_Q);
    cudaGetSymbolAddress((void**)&pK,  g_K);
    cudaGetSymbolAddress((void**)&pV,  g_V);
    cudaGetSymbolAddress((void**)&pKT, g_KT);
    cudaGetSymbolAddress((void**)&pO,  g_O);
    cudaGetSymbolAddress((void**)&pD,  g_Dsm);

    // #0: fused pack
    pack3_kernel<<<dim3(256, 3), 256>>>(Wq_d, Wq_a, bq_d, bq_a,
                                        Wk_d, Wk_a, bk_d, bk_a,
                                        Wv_d, Wv_a, bv_d, bv_a,
                                        pWq, pbq, pWk, pbk, pWv, pbv);
    // #1-3: projections
    dim3 ggrid(128, 2);
    gemm2_kernel<<<ggrid, 256>>>(q_ori, pWq, pbq, pQ);
    gemm2_kernel<<<ggrid, 256>>>(k_ori, pWk, pbk, pK);
    gemm2_kernel<<<ggrid, 256>>>(v_ori, pWv, pbv, pV);

    // #4: fused dist-softmax + K-transpose
    prep_kernel<<<16384 + 4096, 256>>>(dist, mask, pK, pD, pKT);

    // #5: fused attention (mma.sync tf32)
    const int SMEM_BYTES = 26560 * 4;   // 106,240 B -> 2 CTAs/SM
    cudaFuncSetAttribute(attn_kernel, cudaFuncAttributeMaxDynamicSharedMemorySize, SMEM_BYTES);
    dim3 agrid(64, 8, 16);
    attn_kernel<<<agrid, 256, SMEM_BYTES>>>(pQ, pKT, pV, mask, pD, adj, attnw, pO);

    // #6: output projection
    gemm2_kernel<<<ggrid, 256>>>(pO, Wo, bo, out);
}

// round 5
// speedup vs baseline: 1.7552x; 1.2087x over previous
#include <cuda_runtime.h>
#include <cstddef>

// Problem constants
#define BB   16
#define SS   1024
#define DM   256
#define BSN  (BB*SS)             // 16384
#define OUT_ELEMS   (BSN*DM)     // 4,194,304
#define ATTN_ELEMS  (BB*8*SS*SS) // 134,217,728

typedef unsigned long long u64;

__device__ __forceinline__ u64 pk2(float x, float y) {
    u64 r; asm("mov.b64 %0, {%1,%2};" : "=l"(r) : "f"(x), "f"(y)); return r;
}
__device__ __forceinline__ void up2(u64 v, float& x, float& y) {
    asm("mov.b64 {%0,%1}, %2;" : "=f"(x), "=f"(y) : "l"(v));
}
__device__ __forceinline__ void ffma2(u64& d, u64 a, u64 b) {
    asm("fma.rn.f32x2 %0, %1, %2, %0;" : "+l"(d) : "l"(a), "l"(b));
}
__device__ __forceinline__ float to_tf32(float x) {
    float r; asm("cvt.rna.tf32.f32 %0, %1;" : "=f"(r) : "f"(x)); return r;
}
__device__ __forceinline__ void mma_tf32(float* d, float a0, float a1, float a2, float a3,
                                         float b0, float b1) {
    asm("mma.sync.aligned.m16n8k8.row.col.f32.tf32.tf32.f32 "
        "{%0,%1,%2,%3}, {%4,%5,%6,%7}, {%8,%9}, {%0,%1,%2,%3};"
        : "+f"(d[0]), "+f"(d[1]), "+f"(d[2]), "+f"(d[3])
        : "r"(__float_as_uint(a0)), "r"(__float_as_uint(a1)),
          "r"(__float_as_uint(a2)), "r"(__float_as_uint(a3)),
          "r"(__float_as_uint(b0)), "r"(__float_as_uint(b1)));
}

// ---------------- scratch (static device memory; no allocation) -------------
__device__ float g_Wq[256*256], g_Wk[256*256], g_Wv[256*256];
__device__ float g_bq[256],     g_bk[256],     g_bv[256];
__device__ float g_Q [BSN*DM];
__device__ float g_K [BSN*DM];
__device__ float g_V [BSN*DM];
__device__ float g_KT[BSN*DM];            // (b, n, s)
__device__ float g_O [BSN*DM];            // concat(o_dist, o_adj)
__device__ float g_Dsm[(size_t)BB*SS*SS]; // softmax(dist + neg)

// ---------------- fused weight packing ---------------------------------------
__global__ void pack3_kernel(
    const float* __restrict__ Wqd, const float* __restrict__ Wqa,
    const float* __restrict__ bqd, const float* __restrict__ bqa,
    const float* __restrict__ Wkd, const float* __restrict__ Wka,
    const float* __restrict__ bkd, const float* __restrict__ bka,
    const float* __restrict__ Wvd, const float* __restrict__ Wva,
    const float* __restrict__ bvd, const float* __restrict__ bva,
    float* __restrict__ Wq, float* __restrict__ bq,
    float* __restrict__ Wk, float* __restrict__ bk,
    float* __restrict__ Wv, float* __restrict__ bv) {
    int k = blockIdx.x, n = threadIdx.x, w = blockIdx.y;
    const float* Wd = (w == 0) ? Wqd : (w == 1) ? Wkd : Wvd;
    const float* Wa = (w == 0) ? Wqa : (w == 1) ? Wka : Wva;
    const float* bd = (w == 0) ? bqd : (w == 1) ? bkd : bvd;
    const float* ba = (w == 0) ? bqa : (w == 1) ? bka : bva;
    float* W    = (w == 0) ? Wq : (w == 1) ? Wk : Wv;
    float* bias = (w == 0) ? bq : (w == 1) ? bk : bv;
    W[k*256 + n] = (n < 128) ? Wd[k*128 + n] : Wa[k*128 + (n-128)];
    if (k == 0) bias[n] = (n < 128) ? bd[n] : ba[n-128];
}

// ---------------- GEMM (measured 58us): 128x128, FFMA2 ----------------------
__global__ __launch_bounds__(256)
void gemm2_kernel(const float* __restrict__ A, const float* __restrict__ W,
                  const float* __restrict__ bias, float* __restrict__ C) {
    __shared__ float As[16][132];
    __shared__ float Ws[16][132];
    const int t  = threadIdx.x;
    const int m0 = blockIdx.x * 128;
    const int n0 = blockIdx.y * 128;
    const int tn = t & 15, tm = t >> 4;

    u64 acc[4][8];
    #pragma unroll
    for (int p = 0; p < 4; ++p)
        #pragma unroll
        for (int j = 0; j < 8; ++j) acc[p][j] = 0ull;

    for (int k0 = 0; k0 < 256; k0 += 16) {
        __syncthreads();
        #pragma unroll
        for (int u = 0; u < 2; ++u) {
            int fi  = t + u*256;
            int row = fi >> 2, c4 = fi & 3;
            float4 v = *(const float4*)(A + (size_t)(m0+row)*256 + k0 + c4*4);
            As[c4*4+0][row] = v.x; As[c4*4+1][row] = v.y;
            As[c4*4+2][row] = v.z; As[c4*4+3][row] = v.w;
        }
        #pragma unroll
        for (int u = 0; u < 2; ++u) {
            int fi = t + u*256;
            int k = fi >> 5, n4 = fi & 31;
            *(float4*)(&Ws[k][n4*4]) =
                *(const float4*)(W + (size_t)(k0+k)*256 + n0 + n4*4);
        }
        __syncthreads();
        #pragma unroll
        for (int k = 0; k < 16; ++k) {
            ulonglong2 a01 = *(const ulonglong2*)(&As[k][tm*8]);
            ulonglong2 a23 = *(const ulonglong2*)(&As[k][tm*8 + 4]);
            u64 ap[4] = {a01.x, a01.y, a23.x, a23.y};
            float4 w0 = *(const float4*)(&Ws[k][tn*8]);
            float4 w1 = *(const float4*)(&Ws[k][tn*8 + 4]);
            u64 bd[8];
            bd[0] = pk2(w0.x, w0.x); bd[1] = pk2(w0.y, w0.y);
            bd[2] = pk2(w0.z, w0.z); bd[3] = pk2(w0.w, w0.w);
            bd[4] = pk2(w1.x, w1.x); bd[5] = pk2(w1.y, w1.y);
            bd[6] = pk2(w1.z, w1.z); bd[7] = pk2(w1.w, w1.w);
            #pragma unroll
            for (int p = 0; p < 4; ++p)
                #pragma unroll
                for (int j = 0; j < 8; ++j)
                    ffma2(acc[p][j], ap[p], bd[j]);
        }
    }
    float4 b0 = *(const float4*)(bias + n0 + tn*8);
    float4 b1 = *(const float4*)(bias + n0 + tn*8 + 4);
    float bb[8] = {b0.x, b0.y, b0.z, b0.w, b1.x, b1.y, b1.z, b1.w};
    #pragma unroll
    for (int p = 0; p < 4; ++p) {
        float lo[8], hi[8];
        #pragma unroll
        for (int j = 0; j < 8; ++j) up2(acc[p][j], lo[j], hi[j]);
        int r0 = m0 + tm*8 + p*2;
        float4 o;
        o.x = lo[0]+bb[0]; o.y = lo[1]+bb[1]; o.z = lo[2]+bb[2]; o.w = lo[3]+bb[3];
        *(float4*)(C + (size_t)r0*256 + n0 + tn*8) = o;
        o.x = lo[4]+bb[4]; o.y = lo[5]+bb[5]; o.z = lo[6]+bb[6]; o.w = lo[7]+bb[7];
        *(float4*)(C + (size_t)r0*256 + n0 + tn*8 + 4) = o;
        o.x = hi[0]+bb[0]; o.y = hi[1]+bb[1]; o.z = hi[2]+bb[2]; o.w = hi[3]+bb[3];
        *(float4*)(C + (size_t)(r0+1)*256 + n0 + tn*8) = o;
        o.x = hi[4]+bb[4]; o.y = hi[5]+bb[5]; o.z = hi[6]+bb[6]; o.w = hi[7]+bb[7];
        *(float4*)(C + (size_t)(r0+1)*256 + n0 + tn*8 + 4) = o;
    }
}

// ---------------- prep: dist softmax + K transpose (fused launch) -----------
__global__ __launch_bounds__(256)
void prep_kernel(const float* __restrict__ dist, const float* __restrict__ mask,
                 const float* __restrict__ Kp, float* __restrict__ Dsm,
                 float* __restrict__ KT) {
    __shared__ float tile[32][33];
    __shared__ float ws[8];
    const int blk = blockIdx.x;
    const int t = threadIdx.x;
    if (blk < 16384) {
        const int b = blk >> 10, q = blk & 1023;
        const float* drow = dist + ((size_t)b*SS + q)*SS;
        const float* mrow = mask + (size_t)b*SS;
        float e[4], s = 0.f;
        #pragma unroll
        for (int u = 0; u < 4; ++u) {
            int k = t + u*256;
            e[u] = __expf(drow[k] + mrow[k] * -1e9f);
            s += e[u];
        }
        #pragma unroll
        for (int off = 16; off; off >>= 1) s += __shfl_xor_sync(0xffffffffu, s, off);
        if ((t & 31) == 0) ws[t >> 5] = s;
        __syncthreads();
        float tot = 0.f;
        #pragma unroll
        for (int w = 0; w < 8; ++w) tot += ws[w];
        const float inv = 1.f / tot;
        float* orow = Dsm + ((size_t)b*SS + q)*SS;
        #pragma unroll
        for (int u = 0; u < 4; ++u) orow[t + u*256] = e[u] * inv;
    } else {
        const int r  = (blk - 16384) & 255;
        const int b  = (blk - 16384) >> 8;
        const int n0 = (r & 7) * 32;
        const int s0 = (r >> 3) * 32;
        const int tx = t & 31, ty = t >> 5;
        const float* src = Kp + ((size_t)b*SS + s0)*256 + n0;
        #pragma unroll
        for (int i = 0; i < 32; i += 8)
            tile[ty+i][tx] = src[(size_t)(ty+i)*256 + tx];
        __syncthreads();
        float* dst = KT + ((size_t)b*256 + n0)*SS + s0;
        #pragma unroll
        for (int i = 0; i < 32; i += 8)
            dst[(size_t)(ty+i)*SS + tx] = tile[tx][ty+i];
    }
}

// ---------------- fused attention: 64 queries/CTA, two-pass streaming -------
// CTA = 64 queries x 1 head. 8 warps: mq = warp&3 (16-query m-tile),
// nh = warp>>2 (64-key half of each 128-key tile).
// Pass 1: stream 8 key tiles, QK^T (tf32 mma) -> exp -> row sums.
// Pass 2: recompute logits, w = p*inv*extra -> attn_w + smem w-tile -> PV mma.
// smem floats: q_sm 64x36 | k_sm 32x136 | v_sm 128x40 | w_tl 64x132 (also
// partials 8x544) | msk 1024 | redu 192.  Total 21440 fl = 85,760 B.
__global__ __launch_bounds__(256, 2)
void attn_kernel(const float* __restrict__ Q, const float* __restrict__ KT,
                 const float* __restrict__ V, const float* __restrict__ mask,
                 const float* __restrict__ extraD, const float* __restrict__ extraA,
                 float* __restrict__ attnw, float* __restrict__ Obuf) {
    extern __shared__ float sm[];
    float* q_sm = sm;              // 2304
    float* k_sm = sm + 2304;       // 4352 (stride 136)
    float* v_sm = sm + 6656;       // 5120 (stride 40)
    float* w_tl = sm + 11776;      // 8448 (stride 132; reused as partials 8x544)
    float* msk  = sm + 20224;      // 1024
    float* redu = sm + 21248;      // 192

    const int t    = threadIdx.x;
    const int lane = t & 31, warp = t >> 5;
    const int g = lane >> 2, c = lane & 3;
    const int mq = warp & 3, nh = warp >> 2;
    const int q0 = blockIdx.x * 64;
    const int hg = blockIdx.y;
    const int b  = blockIdx.z;
    const int coloff = hg * 32;
    const float* extra = (hg >= 4) ? extraA : extraD;

    // stage Q (tf32) and mask*-1e9
    #pragma unroll
    for (int u = 0; u < 8; ++u) {
        int i = t + u*256;
        int r = i >> 5, d = i & 31;
        q_sm[r*36 + d] = to_tf32(Q[(size_t)(b*SS + q0 + r)*256 + coloff + d]);
    }
    #pragma unroll
    for (int u = 0; u < 4; ++u)
        msk[t + u*256] = mask[b*SS + t + u*256] * -1e9f;

    const float* ktb   = KT + ((size_t)b*256 + coloff)*SS;
    const float* vbase = V + (size_t)b*SS*256 + coloff;
    const float scale = 0.17677669529663688f;  // 1/sqrt(32)

    const int rlo = mq*16 + g;         // local query rows this thread owns
    const int rhi = rlo + 8;

    // =================== PASS 1: row sums ===================
    float s_lo = 0.f, s_hi = 0.f;
    for (int tile = 0; tile < 8; ++tile) {
        __syncthreads();
        #pragma unroll
        for (int u = 0; u < 4; ++u) {      // stage K tile: 32 dims x 128 keys
            int fi = t + u*256;
            int kd = fi >> 5, c4 = fi & 31;
            float4 v = *(const float4*)(ktb + (size_t)kd*SS + tile*128 + c4*4);
            v.x = to_tf32(v.x); v.y = to_tf32(v.y);
            v.z = to_tf32(v.z); v.w = to_tf32(v.w);
            *(float4*)(&k_sm[kd*136 + c4*4]) = v;
        }
        __syncthreads();
        float acc[8][4];
        #pragma unroll
        for (int nt = 0; nt < 8; ++nt)
            #pragma unroll
            for (int j = 0; j < 4; ++j) acc[nt][j] = 0.f;
        #pragma unroll
        for (int ks = 0; ks < 4; ++ks) {
            float a0 = q_sm[rlo*36 + ks*8 + c];
            float a1 = q_sm[rhi*36 + ks*8 + c];
            float a2 = q_sm[rlo*36 + ks*8 + c + 4];
            float a3 = q_sm[rhi*36 + ks*8 + c + 4];
            #pragma unroll
            for (int nt = 0; nt < 8; ++nt) {
                int n0 = nh*64 + nt*8 + g;
                float b0 = k_sm[(ks*8 + c)*136 + n0];
                float b1 = k_sm[(ks*8 + c + 4)*136 + n0];
                mma_tf32(acc[nt], a0, a1, a2, a3, b0, b1);
            }
        }
        #pragma unroll
        for (int nt = 0; nt < 8; ++nt) {
            int key0 = tile*128 + nh*64 + nt*8 + c*2;
            float n0v = msk[key0], n1v = msk[key0+1];
            s_lo += __expf(fmaf(acc[nt][0], scale, n0v));
            s_lo += __expf(fmaf(acc[nt][1], scale, n1v));
            s_hi += __expf(fmaf(acc[nt][2], scale, n0v));
            s_hi += __expf(fmaf(acc[nt][3], scale, n1v));
        }
    }
    s_lo += __shfl_xor_sync(0xffffffffu, s_lo, 1);
    s_lo += __shfl_xor_sync(0xffffffffu, s_lo, 2);
    s_hi += __shfl_xor_sync(0xffffffffu, s_hi, 1);
    s_hi += __shfl_xor_sync(0xffffffffu, s_hi, 2);
    if (c == 0) {
        redu[nh*64 + rlo] = s_lo;
        redu[nh*64 + rhi] = s_hi;
    }
    __syncthreads();
    if (t < 64) redu[128 + t] = 1.f / (redu[t] + redu[64 + t]);

    const float* exlo = extra + ((size_t)b*SS + q0 + rlo)*SS;
    const float* exhi = extra + ((size_t)b*SS + q0 + rhi)*SS;
    float* wplo = attnw ? attnw + ((size_t)(b*8 + hg)*SS + q0 + rlo)*SS : (float*)0;
    float* wphi = attnw ? attnw + ((size_t)(b*8 + hg)*SS + q0 + rhi)*SS : (float*)0;

    // =================== PASS 2: weights + PV ===================
    float oc[4][4];
    #pragma unroll
    for (int nt = 0; nt < 4; ++nt)
        #pragma unroll
        for (int j = 0; j < 4; ++j) oc[nt][j] = 0.f;

    __syncthreads();
    const float inv_lo = redu[128 + rlo];
    const float inv_hi = redu[128 + rhi];

    for (int tile = 0; tile < 8; ++tile) {
        __syncthreads();
        #pragma unroll
        for (int u = 0; u < 4; ++u) {      // re-stage K tile
            int fi = t + u*256;
            int kd = fi >> 5, c4 = fi & 31;
            float4 v = *(const float4*)(ktb + (size_t)kd*SS + tile*128 + c4*4);
            v.x = to_tf32(v.x); v.y = to_tf32(v.y);
            v.z = to_tf32(v.z); v.w = to_tf32(v.w);
            *(float4*)(&k_sm[kd*136 + c4*4]) = v;
        }
        #pragma unroll
        for (int u = 0; u < 4; ++u) {      // stage V tile: 128 keys x 32 dims
            int fi = t + u*256;
            int kr = fi >> 3, q4 = fi & 7;
            float4 v = *(const float4*)(vbase + (size_t)(tile*128 + kr)*256 + q4*4);
            v.x = to_tf32(v.x); v.y = to_tf32(v.y);
            v.z = to_tf32(v.z); v.w = to_tf32(v.w);
            *(float4*)(&v_sm[kr*40 + q4*4]) = v;
        }
        __syncthreads();
        float acc[8][4];
        #pragma unroll
        for (int nt = 0; nt < 8; ++nt)
            #pragma unroll
            for (int j = 0; j < 4; ++j) acc[nt][j] = 0.f;
        #pragma unroll
        for (int ks = 0; ks < 4; ++ks) {
            float a0 = q_sm[rlo*36 + ks*8 + c];
            float a1 = q_sm[rhi*36 + ks*8 + c];
            float a2 = q_sm[rlo*36 + ks*8 + c + 4];
            float a3 = q_sm[rhi*36 + ks*8 + c + 4];
            #pragma unroll
            for (int nt = 0; nt < 8; ++nt) {
                int n0 = nh*64 + nt*8 + g;
                float b0 = k_sm[(ks*8 + c)*136 + n0];
                float b1 = k_sm[(ks*8 + c + 4)*136 + n0];
                mma_tf32(acc[nt], a0, a1, a2, a3, b0, b1);
            }
        }
        // w = exp(...)*inv*extra -> attn_w + w_tl
        #pragma unroll
        for (int nt = 0; nt < 8; ++nt) {
            int lkey = nh*64 + nt*8 + c*2;       // key within tile
            int key0 = tile*128 + lkey;
            float n0v = msk[key0], n1v = msk[key0+1];
            float2 elo = *(const float2*)(exlo + key0);
            float2 ehi = *(const float2*)(exhi + key0);
            float w0 = __expf(fmaf(acc[nt][0], scale, n0v)) * inv_lo * elo.x;
            float w1 = __expf(fmaf(acc[nt][1], scale, n1v)) * inv_lo * elo.y;
            float w2 = __expf(fmaf(acc[nt][2], scale, n0v)) * inv_hi * ehi.x;
            float w3 = __expf(fmaf(acc[nt][3], scale, n1v)) * inv_hi * ehi.y;
            if (wplo) {
                float2 o; o.x = w0; o.y = w1; *(float2*)(wplo + key0) = o;
                o.x = w2; o.y = w3; *(float2*)(wphi + key0) = o;
            }
            float2 s;
            s.x = to_tf32(w0); s.y = to_tf32(w1);
            *(float2*)(&w_tl[rlo*132 + lkey]) = s;
            s.x = to_tf32(w2); s.y = to_tf32(w3);
            *(float2*)(&w_tl[rhi*132 + lkey]) = s;
        }
        __syncthreads();
        // PV: oc += w_tl[mq-tile][nh-half keys] @ v_sm
        #pragma unroll
        for (int ks = 0; ks < 8; ++ks) {
            int kb = nh*64 + ks*8;               // key base within tile
            float a0 = w_tl[rlo*132 + kb + c];
            float a1 = w_tl[rhi*132 + kb + c];
            float a2 = w_tl[rlo*132 + kb + c + 4];
            float a3 = w_tl[rhi*132 + kb + c + 4];
            #pragma unroll
            for (int nt = 0; nt < 4; ++nt) {
                float b0 = v_sm[(kb + c)*40 + nt*8 + g];
                float b1 = v_sm[(kb + c + 4)*40 + nt*8 + g];
                mma_tf32(oc[nt], a0, a1, a2, a3, b0, b1);
            }
        }
    }

    // ---- cross-half key reduction (warps mq and mq+4) via smem ----
    __syncthreads();                     // w_tl free -> partials [8][544]
    #pragma unroll
    for (int nt = 0; nt < 4; ++nt) {
        float2 o;
        o.x = oc[nt][0]; o.y = oc[nt][1];
        *(float2*)(&w_tl[warp*544 + g*34 + nt*8 + c*2]) = o;
        o.x = oc[nt][2]; o.y = oc[nt][3];
        *(float2*)(&w_tl[warp*544 + (g+8)*34 + nt*8 + c*2]) = o;
    }
    __syncthreads();
    #pragma unroll
    for (int u = 0; u < 8; ++u) {
        int slot = t + u*256;
        int r = slot >> 5, d = slot & 31;
        int m4 = r >> 4, r16 = r & 15;
        float s = w_tl[m4*544 + r16*34 + d] + w_tl[(m4+4)*544 + r16*34 + d];
        Obuf[(size_t)(b*SS + q0 + r)*256 + coloff + d] = s;
    }
}

// ---------------- launch --------------------------------------------------
extern "C" void kernel_launch(void* const* d_in, const int* in_sizes, int n_in,
                              void* d_out, int out_size) {
    const float* v_ori = (const float*)d_in[0];
    const float* k_ori = (const float*)d_in[1];
    const float* q_ori = (const float*)d_in[2];
    const float* mask  = (const float*)d_in[3];
    const float* adj   = (const float*)d_in[4];
    const float* dist  = (const float*)d_in[5];
    const float* Wq_d = (const float*)d_in[6];  const float* bq_d = (const float*)d_in[7];
    const float* Wk_d = (const float*)d_in[8];  const float* bk_d = (const float*)d_in[9];
    const float* Wv_d = (const float*)d_in[10]; const float* bv_d = (const float*)d_in[11];
    const float* Wq_a = (const float*)d_in[12]; const float* bq_a = (const float*)d_in[13];
    const float* Wk_a = (const float*)d_in[14]; const float* bk_a = (const float*)d_in[15];
    const float* Wv_a = (const float*)d_in[16]; const float* bv_a = (const float*)d_in[17];
    const float* Wo   = (const float*)d_in[18]; const float* bo   = (const float*)d_in[19];

    float* out   = (float*)d_out;
    float* attnw = (out_size >= OUT_ELEMS + ATTN_ELEMS) ? out + OUT_ELEMS : (float*)0;

    float *pWq,*pWk,*pWv,*pbq,*pbk,*pbv,*pQ,*pK,*pV,*pKT,*pO,*pD;
    cudaGetSymbolAddress((void**)&pWq, g_Wq);
    cudaGetSymbolAddress((void**)&pWk, g_Wk);
    cudaGetSymbolAddress((void**)&pWv, g_Wv);
    cudaGetSymbolAddress((void**)&pbq, g_bq);
    cudaGetSymbolAddress((void**)&pbk, g_bk);
    cudaGetSymbolAddress((void**)&pbv, g_bv);
    cudaGetSymbolAddress((void**)&pQ,  g_Q);
    cudaGetSymbolAddress((void**)&pK,  g_K);
    cudaGetSymbolAddress((void**)&pV,  g_V);
    cudaGetSymbolAddress((void**)&pKT, g_KT);
    cudaGetSymbolAddress((void**)&pO,  g_O);
    cudaGetSymbolAddress((void**)&pD,  g_Dsm);

    // #0: fused pack
    pack3_kernel<<<dim3(256, 3), 256>>>(Wq_d, Wq_a, bq_d, bq_a,
                                        Wk_d, Wk_a, bk_d, bk_a,
                                        Wv_d, Wv_a, bv_d, bv_a,
                                        pWq, pbq, pWk, pbk, pWv, pbv);
    // #1-3: projections
    dim3 ggrid(128, 2);
    gemm2_kernel<<<ggrid, 256>>>(q_ori, pWq, pbq, pQ);
    gemm2_kernel<<<ggrid, 256>>>(k_ori, pWk, pbk, pK);
    gemm2_kernel<<<ggrid, 256>>>(v_ori, pWv, pbv, pV);

    // #4: fused dist-softmax + K-transpose
    prep_kernel<<<16384 + 4096, 256>>>(dist, mask, pK, pD, pKT);

    // #5: fused attention (two-pass streaming, mma.sync tf32)
    const int SMEM_BYTES = 21440 * 4;   // 85,760 B -> 2 CTAs/SM
    cudaFuncSetAttribute(attn_kernel, cudaFuncAttributeMaxDynamicSharedMemorySize, SMEM_BYTES);
    dim3 agrid(16, 8, 16);
    attn_kernel<<<agrid, 256, SMEM_BYTES>>>(pQ, pKT, pV, mask, pD, adj, attnw, pO);

    // #6: output projection
    gemm2_kernel<<<ggrid, 256>>>(pO, Wo, bo, out);
}